// round 11
// baseline (speedup 1.0000x reference)
#include <cuda_runtime.h>
#include <cuda_bf16.h>
#include <math.h>

#define NQ   16384
#define NF   8192
#define DD   64
#define TOPK 16
#define KNN  5

#define BM 128
#define BN 128
#define PADQ 132                       // floats per feature row (33 float4s, odd quads -> conflict-free)
#define SMEM_BYTES (2 * 64 * PADQ * 4) // 67584 bytes dynamic

// ---------------- scratch (__device__ globals; no runtime allocation) -------
__device__ float g_Xc[(size_t)NQ * DD];
__device__ float g_Fc[(size_t)NF * DD];
__device__ float g_SqX[NQ];
__device__ float g_SqF[NF];
__device__ unsigned long long g_qbits[NQ];
__device__ unsigned long long g_fbits[NF];
__device__ float g_key[(size_t)NQ * NF];      // 512 MB distance-key matrix
__device__ int   g_topIdx[(size_t)NQ * TOPK];
__device__ float g_colmean[DD];

__device__ __forceinline__ float f_inf() { return __int_as_float(0x7f800000); }

// ---------------- packed fp32x2 helpers (sm_103a) ----------------------------
__device__ __forceinline__ unsigned long long pk2(float a, float b) {
    unsigned long long r;
    asm("mov.b64 %0, {%1, %2};" : "=l"(r) : "f"(a), "f"(b));
    return r;
}
__device__ __forceinline__ unsigned long long fma2(unsigned long long a,
                                                   unsigned long long b,
                                                   unsigned long long c) {
    unsigned long long d;
    asm("fma.rn.f32x2 %0, %1, %2, %3;" : "=l"(d) : "l"(a), "l"(b), "l"(c));
    return d;
}
__device__ __forceinline__ unsigned long long add2(unsigned long long a,
                                                   unsigned long long b) {
    unsigned long long d;
    asm("add.rn.f32x2 %0, %1, %2;" : "=l"(d) : "l"(a), "l"(b));
    return d;
}

// ---------------- prep: clean values, observed bitmask, sum of squares ------
__global__ void prep_kernel(const float* __restrict__ src, int nrows, int isX)
{
    int w    = (blockIdx.x * blockDim.x + threadIdx.x) >> 5;
    int lane = threadIdx.x & 31;
    if (w >= nrows) return;

    float* clean             = isX ? g_Xc : g_Fc;
    float* sq                = isX ? g_SqX : g_SqF;
    unsigned long long* bits = isX ? g_qbits : g_fbits;

    const float* row = src + (size_t)w * DD;
    float v0 = row[lane];
    float v1 = row[lane + 32];
    bool  o0 = !isnan(v0);
    bool  o1 = !isnan(v1);
    float c0 = o0 ? v0 : 0.0f;
    float c1 = o1 ? v1 : 0.0f;
    clean[(size_t)w * DD + lane]      = c0;
    clean[(size_t)w * DD + lane + 32] = c1;

    unsigned ob0 = __ballot_sync(0xffffffffu, o0);
    unsigned ob1 = __ballot_sync(0xffffffffu, o1);

    float s = c0 * c0 + c1 * c1;
    #pragma unroll
    for (int o = 16; o > 0; o >>= 1) s += __shfl_xor_sync(0xffffffffu, s, o);

    if (lane == 0) {
        bits[w] = (unsigned long long)ob0 | ((unsigned long long)ob1 << 32);
        sq[w]   = s;
    }
}

// ---------------- per-column mean of observed fit values (fallback) ---------
__global__ void colmean_kernel(const float* __restrict__ fit)
{
    int c   = blockIdx.x;
    int tid = threadIdx.x;
    float s = 0.0f;
    int   n = 0;
    for (int r = tid; r < NF; r += 256) {
        float v = fit[(size_t)r * DD + c];
        if (!isnan(v)) { s += v; n++; }
    }
    __shared__ float ss[256];
    __shared__ int   sn[256];
    ss[tid] = s; sn[tid] = n;
    __syncthreads();
    for (int o = 128; o > 0; o >>= 1) {
        if (tid < o) { ss[tid] += ss[tid + o]; sn[tid] += sn[tid + o]; }
        __syncthreads();
    }
    if (tid == 0) g_colmean[c] = (sn[0] > 0) ? ss[0] / (float)sn[0] : 0.0f;
}

// ---------------- distance-key kernel: GEMM + sparse mask corrections -------
// key[q][r] = max(SqX+SqF-2*s - corrB - corrC, 0) * 64/cnt ; +inf if cnt==0
union AccRow {
    unsigned long long u[4];
    float              f[8];
};

__global__ __launch_bounds__(256, 2) void dist_kernel()
{
    extern __shared__ float sm[];
    float* Xs = sm;                 // [64][PADQ] feature-major query tile
    float* Ys = sm + 64 * PADQ;     // [64][PADQ] feature-major fit tile
    __shared__ unsigned long long sQb[BM];
    __shared__ unsigned long long sFb[BN];

    int tid = threadIdx.x;
    int tx = tid & 15;
    int ty = tid >> 4;
    int qbase = blockIdx.y * BM;
    int rbase = blockIdx.x * BN;

    #pragma unroll
    for (int it = 0; it < 8; ++it) {
        int e  = tid + it * 256;
        int f  = e & 63;
        int q4 = (e >> 6) << 2;
        const float* gx = g_Xc + (size_t)(qbase + q4) * DD + f;
        const float* gf = g_Fc + (size_t)(rbase + q4) * DD + f;
        float4 v, w;
        v.x = gx[0]; v.y = gx[DD]; v.z = gx[2 * DD]; v.w = gx[3 * DD];
        w.x = gf[0]; w.y = gf[DD]; w.z = gf[2 * DD]; w.w = gf[3 * DD];
        *(float4*)&Xs[f * PADQ + q4] = v;
        *(float4*)&Ys[f * PADQ + q4] = w;
    }
    if (tid < BM) sQb[tid] = g_qbits[qbase + tid];
    else if (tid < BM + BN) sFb[tid - BM] = g_fbits[rbase + tid - BM];
    __syncthreads();

    const float4* X4 = (const float4*)Xs;
    const float4* Y4 = (const float4*)Ys;

    AccRow acc[8];
    #pragma unroll
    for (int i = 0; i < 8; i++)
        #pragma unroll
        for (int p = 0; p < 4; p++) acc[i].u[p] = 0ull;

    #pragma unroll 8
    for (int f = 0; f < DD; ++f) {
        float4 xa = X4[f * 33 + ty];
        float4 xb = X4[f * 33 + 16 + ty];
        float4 ya = Y4[f * 33 + tx];
        float4 yb = Y4[f * 33 + 16 + tx];
        unsigned long long y01 = pk2(ya.x, ya.y);
        unsigned long long y23 = pk2(ya.z, ya.w);
        unsigned long long y45 = pk2(yb.x, yb.y);
        unsigned long long y67 = pk2(yb.z, yb.w);
        float xs[8] = {xa.x, xa.y, xa.z, xa.w, xb.x, xb.y, xb.z, xb.w};
        #pragma unroll
        for (int i = 0; i < 8; ++i) {
            unsigned long long xx = pk2(xs[i], xs[i]);
            acc[i].u[0] = fma2(xx, y01, acc[i].u[0]);
            acc[i].u[1] = fma2(xx, y23, acc[i].u[1]);
            acc[i].u[2] = fma2(xx, y45, acc[i].u[2]);
            acc[i].u[3] = fma2(xx, y67, acc[i].u[3]);
        }
    }

    {
        const unsigned long long NEG2 = pk2(-2.0f, -2.0f);
        unsigned long long sf2[4];
        #pragma unroll
        for (int p = 0; p < 4; p++) {
            int c0 = (p < 2) ? 4 * tx + 2 * p : 60 + 4 * tx + 2 * p;
            sf2[p] = pk2(g_SqF[rbase + c0], g_SqF[rbase + c0 + 1]);
        }
        #pragma unroll
        for (int i = 0; i < 8; i++) {
            int row = (i < 4) ? 4 * ty + i : 60 + 4 * ty + i;
            float sx = g_SqX[qbase + row];
            unsigned long long sx2 = pk2(sx, sx);
            #pragma unroll
            for (int p = 0; p < 4; p++)
                acc[i].u[p] = fma2(acc[i].u[p], NEG2, add2(sx2, sf2[p]));
        }
    }

    #pragma unroll
    for (int j = 0; j < 8; ++j) {
        int col = (j < 4) ? 4 * tx + j : 60 + 4 * tx + j;
        unsigned long long fb = sFb[col];
        unsigned mlo = ~(unsigned)fb;
        unsigned mhi = ~(unsigned)(fb >> 32);
        #pragma unroll 1
        for (int h = 0; h < 2; ++h) {
            unsigned mm = h ? mhi : mlo;
            int base = h ? 32 : 0;
            while (mm) {
                int f = base + __ffs(mm) - 1; mm &= mm - 1;
                float4 xa = X4[f * 33 + ty];
                float4 xb = X4[f * 33 + 16 + ty];
                acc[0].f[j] = fmaf(-xa.x, xa.x, acc[0].f[j]);
                acc[1].f[j] = fmaf(-xa.y, xa.y, acc[1].f[j]);
                acc[2].f[j] = fmaf(-xa.z, xa.z, acc[2].f[j]);
                acc[3].f[j] = fmaf(-xa.w, xa.w, acc[3].f[j]);
                acc[4].f[j] = fmaf(-xb.x, xb.x, acc[4].f[j]);
                acc[5].f[j] = fmaf(-xb.y, xb.y, acc[5].f[j]);
                acc[6].f[j] = fmaf(-xb.z, xb.z, acc[6].f[j]);
                acc[7].f[j] = fmaf(-xb.w, xb.w, acc[7].f[j]);
            }
        }
    }
    #pragma unroll
    for (int i = 0; i < 8; ++i) {
        int row = (i < 4) ? 4 * ty + i : 60 + 4 * ty + i;
        unsigned long long qb = sQb[row];
        unsigned mlo = ~(unsigned)qb;
        unsigned mhi = ~(unsigned)(qb >> 32);
        #pragma unroll 1
        for (int h = 0; h < 2; ++h) {
            unsigned mm = h ? mhi : mlo;
            int base = h ? 32 : 0;
            while (mm) {
                int f = base + __ffs(mm) - 1; mm &= mm - 1;
                float4 ya = Y4[f * 33 + tx];
                float4 yb = Y4[f * 33 + 16 + tx];
                acc[i].f[0] = fmaf(-ya.x, ya.x, acc[i].f[0]);
                acc[i].f[1] = fmaf(-ya.y, ya.y, acc[i].f[1]);
                acc[i].f[2] = fmaf(-ya.z, ya.z, acc[i].f[2]);
                acc[i].f[3] = fmaf(-ya.w, ya.w, acc[i].f[3]);
                acc[i].f[4] = fmaf(-yb.x, yb.x, acc[i].f[4]);
                acc[i].f[5] = fmaf(-yb.y, yb.y, acc[i].f[5]);
                acc[i].f[6] = fmaf(-yb.z, yb.z, acc[i].f[6]);
                acc[i].f[7] = fmaf(-yb.w, yb.w, acc[i].f[7]);
            }
        }
    }

    unsigned flo[8], fhi[8];
    #pragma unroll
    for (int j = 0; j < 8; j++) {
        int col = (j < 4) ? 4 * tx + j : 60 + 4 * tx + j;
        unsigned long long fb = sFb[col];
        flo[j] = (unsigned)fb;
        fhi[j] = (unsigned)(fb >> 32);
    }
    #pragma unroll
    for (int i = 0; i < 8; i++) {
        int row = (i < 4) ? 4 * ty + i : 60 + 4 * ty + i;
        unsigned long long qb = sQb[row];
        unsigned qlo = (unsigned)qb, qhi = (unsigned)(qb >> 32);
        float k[8];
        #pragma unroll
        for (int j = 0; j < 8; j++) {
            int n = __popc(qlo & flo[j]) + __popc(qhi & fhi[j]);
            float d2 = fmaxf(acc[i].f[j], 0.0f) * 64.0f;
            k[j] = (n > 0) ? __fdividef(d2, (float)n) : f_inf();
        }
        size_t rowoff = (size_t)(qbase + row) * NF + rbase;
        float4 o0 = {k[0], k[1], k[2], k[3]};
        float4 o1 = {k[4], k[5], k[6], k[7]};
        *(float4*)&g_key[rowoff + 4 * tx]      = o0;
        *(float4*)&g_key[rowoff + 64 + 4 * tx] = o1;
    }
}

// ---------------- top-16 per query: warp per query, batched min-filter ------
// Per iteration: 4 independent LDG.128 (no control flow between them), quad
// mins via FMNMX tree, rare insert path. Keys are nonneg or +inf, so float
// ordering == uint ordering.
__global__ __launch_bounds__(256) void topk_kernel()
{
    int q    = blockIdx.x * 8 + (threadIdx.x >> 5);
    int lane = threadIdx.x & 31;
    const float4* row4 = (const float4*)(g_key + (size_t)q * NF);

    unsigned bd[8];
    int      bi[8];
    #pragma unroll
    for (int j = 0; j < 8; j++) { bd[j] = 0xFFFFFFFFu; bi[j] = -1; }

    // 2048 float4 per row; 64 per lane; 4 per iteration, 16 iterations
    #pragma unroll 2
    for (int k = 0; k < 16; k++) {
        float4 v[4];
        #pragma unroll
        for (int u = 0; u < 4; u++)
            v[u] = row4[lane + ((4 * k + u) << 5)];
        #pragma unroll
        for (int u = 0; u < 4; u++) {
            float m = fminf(fminf(v[u].x, v[u].y), fminf(v[u].z, v[u].w));
            if (__float_as_uint(m) < bd[7]) {
                int base = (lane + ((4 * k + u) << 5)) << 2;
                float e[4] = {v[u].x, v[u].y, v[u].z, v[u].w};
                #pragma unroll
                for (int t = 0; t < 4; t++) {
                    unsigned uv = __float_as_uint(e[t]);
                    if (uv < bd[7]) {
                        bd[7] = uv; bi[7] = base + t;
                        #pragma unroll
                        for (int j = 7; j > 0; --j) {
                            if (bd[j] < bd[j - 1]) {
                                unsigned tv = bd[j]; bd[j] = bd[j - 1]; bd[j - 1] = tv;
                                int      ti = bi[j]; bi[j] = bi[j - 1]; bi[j - 1] = ti;
                            }
                        }
                    }
                }
            }
        }
    }

    // single warp merge: 16 rounds of head extraction over 32 sorted queues
    int ptr = 0;
    unsigned head = bd[0];
    for (int r = 0; r < TOPK; r++) {
        unsigned m   = __reduce_min_sync(0xffffffffu, head);
        unsigned bal = __ballot_sync(0xffffffffu, head == m);
        int leader   = __ffs(bal) - 1;
        if (lane == leader) {
            g_topIdx[(size_t)q * TOPK + r] = (m < 0x7f800000u) ? bi[ptr] : -1;
            ptr++;
            head = (ptr < 8) ? bd[ptr] : 0xFFFFFFFFu;
        }
    }
}

// ---------------- impute: warp per query, 2 features per lane ---------------
__global__ void impute_kernel(const float* __restrict__ X, float* __restrict__ out)
{
    int q    = blockIdx.x * (blockDim.x >> 5) + (threadIdx.x >> 5);
    int lane = threadIdx.x & 31;
    if (q >= NQ) return;

    int myidx = (lane < TOPK) ? g_topIdx[(size_t)q * TOPK + lane] : -1;

    float v0 = X[(size_t)q * DD + lane];
    float v1 = X[(size_t)q * DD + lane + 32];
    bool  n0 = isnan(v0);
    bool  n1 = isnan(v1);
    float s0 = 0.0f, s1 = 0.0f;
    int   c0 = 0, c1 = 0;

    for (int r = 0; r < TOPK; r++) {
        int i = __shfl_sync(0xffffffffu, myidx, r);
        if (i < 0) break;
        unsigned long long fb = g_fbits[i];
        if (n0 && c0 < KNN && ((fb >> lane) & 1ull)) {
            s0 += g_Fc[(size_t)i * DD + lane]; c0++;
        }
        if (n1 && c1 < KNN && ((fb >> (lane + 32)) & 1ull)) {
            s1 += g_Fc[(size_t)i * DD + lane + 32]; c1++;
        }
        bool done = (!n0 || c0 >= KNN) && (!n1 || c1 >= KNN);
        if (__all_sync(0xffffffffu, done)) break;
    }

    out[(size_t)q * DD + lane]      = n0 ? (c0 ? s0 / (float)c0 : g_colmean[lane])      : v0;
    out[(size_t)q * DD + lane + 32] = n1 ? (c1 ? s1 / (float)c1 : g_colmean[lane + 32]) : v1;
}

// ---------------- launcher ---------------------------------------------------
extern "C" void kernel_launch(void* const* d_in, const int* in_sizes, int n_in,
                              void* d_out, int out_size)
{
    const float* X   = (const float*)d_in[0];
    const float* fit = (const float*)d_in[1];
    float* out = (float*)d_out;
    (void)in_sizes; (void)n_in; (void)out_size;

    cudaFuncSetAttribute(dist_kernel,
                         cudaFuncAttributeMaxDynamicSharedMemorySize, SMEM_BYTES);
    cudaFuncSetAttribute(dist_kernel,
                         cudaFuncAttributePreferredSharedMemoryCarveout,
                         cudaSharedmemCarveoutMaxShared);

    prep_kernel<<<NQ / 8, 256>>>(X, NQ, 1);
    prep_kernel<<<NF / 8, 256>>>(fit, NF, 0);
    colmean_kernel<<<DD, 256>>>(fit);

    dim3 dgrid(NF / BN, NQ / BM);
    dist_kernel<<<dgrid, 256, SMEM_BYTES>>>();

    topk_kernel<<<NQ / 8, 256>>>();

    impute_kernel<<<NQ / 8, 256>>>(X, out);
}

// round 12
// speedup vs baseline: 3.0739x; 3.0739x over previous
#include <cuda_runtime.h>
#include <cuda_bf16.h>
#include <math.h>

#define NQ   16384
#define NF   8192
#define DD   64
#define TOPK 16
#define KNN  5
#define NTILE 64                       // NF / BN column tiles

#define BM 128
#define BN 128
#define PADQ 132                       // floats per feature row (33 float4s, odd quads -> conflict-free)
#define SMEM_BYTES (2 * 64 * PADQ * 4) // 67584 bytes dynamic

// ---------------- scratch (__device__ globals; no runtime allocation) -------
__device__ float g_Xc[(size_t)NQ * DD];
__device__ float g_Fc[(size_t)NF * DD];
__device__ float g_SqX[NQ];
__device__ float g_SqF[NF];
__device__ unsigned long long g_qbits[NQ];
__device__ unsigned long long g_fbits[NF];
__device__ float g_key[(size_t)NQ * NF];       // 512 MB distance-key matrix
__device__ float g_tilemin[(size_t)NQ * NTILE]; // 4 MB per-(query,tile) minima
__device__ int   g_topIdx[(size_t)NQ * TOPK];
__device__ float g_colmean[DD];

__device__ __forceinline__ float f_inf() { return __int_as_float(0x7f800000); }

// ---------------- packed fp32x2 helpers (sm_103a) ----------------------------
__device__ __forceinline__ unsigned long long pk2(float a, float b) {
    unsigned long long r;
    asm("mov.b64 %0, {%1, %2};" : "=l"(r) : "f"(a), "f"(b));
    return r;
}
__device__ __forceinline__ unsigned long long fma2(unsigned long long a,
                                                   unsigned long long b,
                                                   unsigned long long c) {
    unsigned long long d;
    asm("fma.rn.f32x2 %0, %1, %2, %3;" : "=l"(d) : "l"(a), "l"(b), "l"(c));
    return d;
}
__device__ __forceinline__ unsigned long long add2(unsigned long long a,
                                                   unsigned long long b) {
    unsigned long long d;
    asm("add.rn.f32x2 %0, %1, %2;" : "=l"(d) : "l"(a), "l"(b));
    return d;
}

// ---------------- prep: clean values, observed bitmask, sum of squares ------
__global__ void prep_kernel(const float* __restrict__ src, int nrows, int isX)
{
    int w    = (blockIdx.x * blockDim.x + threadIdx.x) >> 5;
    int lane = threadIdx.x & 31;
    if (w >= nrows) return;

    float* clean             = isX ? g_Xc : g_Fc;
    float* sq                = isX ? g_SqX : g_SqF;
    unsigned long long* bits = isX ? g_qbits : g_fbits;

    const float* row = src + (size_t)w * DD;
    float v0 = row[lane];
    float v1 = row[lane + 32];
    bool  o0 = !isnan(v0);
    bool  o1 = !isnan(v1);
    float c0 = o0 ? v0 : 0.0f;
    float c1 = o1 ? v1 : 0.0f;
    clean[(size_t)w * DD + lane]      = c0;
    clean[(size_t)w * DD + lane + 32] = c1;

    unsigned ob0 = __ballot_sync(0xffffffffu, o0);
    unsigned ob1 = __ballot_sync(0xffffffffu, o1);

    float s = c0 * c0 + c1 * c1;
    #pragma unroll
    for (int o = 16; o > 0; o >>= 1) s += __shfl_xor_sync(0xffffffffu, s, o);

    if (lane == 0) {
        bits[w] = (unsigned long long)ob0 | ((unsigned long long)ob1 << 32);
        sq[w]   = s;
    }
}

// ---------------- per-column mean of observed fit values (fallback) ---------
__global__ void colmean_kernel(const float* __restrict__ fit)
{
    int c   = blockIdx.x;
    int tid = threadIdx.x;
    float s = 0.0f;
    int   n = 0;
    for (int r = tid; r < NF; r += 256) {
        float v = fit[(size_t)r * DD + c];
        if (!isnan(v)) { s += v; n++; }
    }
    __shared__ float ss[256];
    __shared__ int   sn[256];
    ss[tid] = s; sn[tid] = n;
    __syncthreads();
    for (int o = 128; o > 0; o >>= 1) {
        if (tid < o) { ss[tid] += ss[tid + o]; sn[tid] += sn[tid + o]; }
        __syncthreads();
    }
    if (tid == 0) g_colmean[c] = (sn[0] > 0) ? ss[0] / (float)sn[0] : 0.0f;
}

// ---------------- distance-key kernel: GEMM + sparse mask corrections -------
// key[q][r] = max(SqX+SqF-2*s - corrB - corrC, 0) * 64/cnt ; +inf if cnt==0
// Also emits per-(row, col-tile) minimum for exact pruning in topk.
union AccRow {
    unsigned long long u[4];
    float              f[8];
};

__global__ __launch_bounds__(256, 2) void dist_kernel()
{
    extern __shared__ float sm[];
    float* Xs = sm;                 // [64][PADQ] feature-major query tile
    float* Ys = sm + 64 * PADQ;     // [64][PADQ] feature-major fit tile
    __shared__ unsigned long long sQb[BM];
    __shared__ unsigned long long sFb[BN];

    int tid = threadIdx.x;
    int tx = tid & 15;
    int ty = tid >> 4;
    int qbase = blockIdx.y * BM;
    int rbase = blockIdx.x * BN;

    #pragma unroll
    for (int it = 0; it < 8; ++it) {
        int e  = tid + it * 256;
        int f  = e & 63;
        int q4 = (e >> 6) << 2;
        const float* gx = g_Xc + (size_t)(qbase + q4) * DD + f;
        const float* gf = g_Fc + (size_t)(rbase + q4) * DD + f;
        float4 v, w;
        v.x = gx[0]; v.y = gx[DD]; v.z = gx[2 * DD]; v.w = gx[3 * DD];
        w.x = gf[0]; w.y = gf[DD]; w.z = gf[2 * DD]; w.w = gf[3 * DD];
        *(float4*)&Xs[f * PADQ + q4] = v;
        *(float4*)&Ys[f * PADQ + q4] = w;
    }
    if (tid < BM) sQb[tid] = g_qbits[qbase + tid];
    else if (tid < BM + BN) sFb[tid - BM] = g_fbits[rbase + tid - BM];
    __syncthreads();

    const float4* X4 = (const float4*)Xs;
    const float4* Y4 = (const float4*)Ys;

    AccRow acc[8];
    #pragma unroll
    for (int i = 0; i < 8; i++)
        #pragma unroll
        for (int p = 0; p < 4; p++) acc[i].u[p] = 0ull;

    #pragma unroll 8
    for (int f = 0; f < DD; ++f) {
        float4 xa = X4[f * 33 + ty];
        float4 xb = X4[f * 33 + 16 + ty];
        float4 ya = Y4[f * 33 + tx];
        float4 yb = Y4[f * 33 + 16 + tx];
        unsigned long long y01 = pk2(ya.x, ya.y);
        unsigned long long y23 = pk2(ya.z, ya.w);
        unsigned long long y45 = pk2(yb.x, yb.y);
        unsigned long long y67 = pk2(yb.z, yb.w);
        float xs[8] = {xa.x, xa.y, xa.z, xa.w, xb.x, xb.y, xb.z, xb.w};
        #pragma unroll
        for (int i = 0; i < 8; ++i) {
            unsigned long long xx = pk2(xs[i], xs[i]);
            acc[i].u[0] = fma2(xx, y01, acc[i].u[0]);
            acc[i].u[1] = fma2(xx, y23, acc[i].u[1]);
            acc[i].u[2] = fma2(xx, y45, acc[i].u[2]);
            acc[i].u[3] = fma2(xx, y67, acc[i].u[3]);
        }
    }

    {
        const unsigned long long NEG2 = pk2(-2.0f, -2.0f);
        unsigned long long sf2[4];
        #pragma unroll
        for (int p = 0; p < 4; p++) {
            int c0 = (p < 2) ? 4 * tx + 2 * p : 60 + 4 * tx + 2 * p;
            sf2[p] = pk2(g_SqF[rbase + c0], g_SqF[rbase + c0 + 1]);
        }
        #pragma unroll
        for (int i = 0; i < 8; i++) {
            int row = (i < 4) ? 4 * ty + i : 60 + 4 * ty + i;
            float sx = g_SqX[qbase + row];
            unsigned long long sx2 = pk2(sx, sx);
            #pragma unroll
            for (int p = 0; p < 4; p++)
                acc[i].u[p] = fma2(acc[i].u[p], NEG2, add2(sx2, sf2[p]));
        }
    }

    #pragma unroll
    for (int j = 0; j < 8; ++j) {
        int col = (j < 4) ? 4 * tx + j : 60 + 4 * tx + j;
        unsigned long long fb = sFb[col];
        unsigned mlo = ~(unsigned)fb;
        unsigned mhi = ~(unsigned)(fb >> 32);
        #pragma unroll 1
        for (int h = 0; h < 2; ++h) {
            unsigned mm = h ? mhi : mlo;
            int base = h ? 32 : 0;
            while (mm) {
                int f = base + __ffs(mm) - 1; mm &= mm - 1;
                float4 xa = X4[f * 33 + ty];
                float4 xb = X4[f * 33 + 16 + ty];
                acc[0].f[j] = fmaf(-xa.x, xa.x, acc[0].f[j]);
                acc[1].f[j] = fmaf(-xa.y, xa.y, acc[1].f[j]);
                acc[2].f[j] = fmaf(-xa.z, xa.z, acc[2].f[j]);
                acc[3].f[j] = fmaf(-xa.w, xa.w, acc[3].f[j]);
                acc[4].f[j] = fmaf(-xb.x, xb.x, acc[4].f[j]);
                acc[5].f[j] = fmaf(-xb.y, xb.y, acc[5].f[j]);
                acc[6].f[j] = fmaf(-xb.z, xb.z, acc[6].f[j]);
                acc[7].f[j] = fmaf(-xb.w, xb.w, acc[7].f[j]);
            }
        }
    }
    #pragma unroll
    for (int i = 0; i < 8; ++i) {
        int row = (i < 4) ? 4 * ty + i : 60 + 4 * ty + i;
        unsigned long long qb = sQb[row];
        unsigned mlo = ~(unsigned)qb;
        unsigned mhi = ~(unsigned)(qb >> 32);
        #pragma unroll 1
        for (int h = 0; h < 2; ++h) {
            unsigned mm = h ? mhi : mlo;
            int base = h ? 32 : 0;
            while (mm) {
                int f = base + __ffs(mm) - 1; mm &= mm - 1;
                float4 ya = Y4[f * 33 + tx];
                float4 yb = Y4[f * 33 + 16 + tx];
                acc[i].f[0] = fmaf(-ya.x, ya.x, acc[i].f[0]);
                acc[i].f[1] = fmaf(-ya.y, ya.y, acc[i].f[1]);
                acc[i].f[2] = fmaf(-ya.z, ya.z, acc[i].f[2]);
                acc[i].f[3] = fmaf(-ya.w, ya.w, acc[i].f[3]);
                acc[i].f[4] = fmaf(-yb.x, yb.x, acc[i].f[4]);
                acc[i].f[5] = fmaf(-yb.y, yb.y, acc[i].f[5]);
                acc[i].f[6] = fmaf(-yb.z, yb.z, acc[i].f[6]);
                acc[i].f[7] = fmaf(-yb.w, yb.w, acc[i].f[7]);
            }
        }
    }

    unsigned flo[8], fhi[8];
    #pragma unroll
    for (int j = 0; j < 8; j++) {
        int col = (j < 4) ? 4 * tx + j : 60 + 4 * tx + j;
        unsigned long long fb = sFb[col];
        flo[j] = (unsigned)fb;
        fhi[j] = (unsigned)(fb >> 32);
    }
    #pragma unroll
    for (int i = 0; i < 8; i++) {
        int row = (i < 4) ? 4 * ty + i : 60 + 4 * ty + i;
        unsigned long long qb = sQb[row];
        unsigned qlo = (unsigned)qb, qhi = (unsigned)(qb >> 32);
        float k[8];
        #pragma unroll
        for (int j = 0; j < 8; j++) {
            int n = __popc(qlo & flo[j]) + __popc(qhi & fhi[j]);
            float d2 = fmaxf(acc[i].f[j], 0.0f) * 64.0f;
            k[j] = (n > 0) ? __fdividef(d2, (float)n) : f_inf();
        }
        size_t rowoff = (size_t)(qbase + row) * NF + rbase;
        float4 o0 = {k[0], k[1], k[2], k[3]};
        float4 o1 = {k[4], k[5], k[6], k[7]};
        *(float4*)&g_key[rowoff + 4 * tx]      = o0;
        *(float4*)&g_key[rowoff + 64 + 4 * tx] = o1;

        // per-(row, tile) minimum: reduce over this thread's 8 cols, then
        // over the 16 consecutive lanes (same ty group) sharing this row
        float rmin = fminf(fminf(fminf(k[0], k[1]), fminf(k[2], k[3])),
                           fminf(fminf(k[4], k[5]), fminf(k[6], k[7])));
        #pragma unroll
        for (int o = 1; o < 16; o <<= 1)
            rmin = fminf(rmin, __shfl_xor_sync(0xffffffffu, rmin, o));
        if (tx == 0)
            g_tilemin[(size_t)(qbase + row) * NTILE + blockIdx.x] = rmin;
    }
}

// ---------------- top-16 per query: exact tile-min prune + R9 scan ----------
// B = 16th smallest of the 64 tile minima (each is a real key from a distinct
// tile => 16th smallest key <= B). Only tiles with min <= B can hold a top-16
// key; exactly 16 (+ties) qualify. Scan those with the proven scalar filter.
__global__ __launch_bounds__(256) void topk_kernel()
{
    int q    = blockIdx.x * 8 + (threadIdx.x >> 5);
    int lane = threadIdx.x & 31;
    const float* row = g_key + (size_t)q * NF;
    const float* tm  = g_tilemin + (size_t)q * NTILE;

    unsigned t0 = __float_as_uint(tm[lane]);
    unsigned t1 = __float_as_uint(tm[lane + 32]);
    unsigned qlo = min(t0, t1), qhi = max(t0, t1);

    // B = 16th smallest of 64 tile minima (warp-uniform after loop)
    unsigned B;
    {
        unsigned head = qlo;
        int ptr = 0;
        unsigned m = 0;
        for (int r = 0; r < TOPK; r++) {
            m = __reduce_min_sync(0xffffffffu, head);
            unsigned bal = __ballot_sync(0xffffffffu, head == m);
            int leader   = __ffs(bal) - 1;
            if (lane == leader) {
                ptr++;
                head = (ptr == 1) ? qhi : 0xFFFFFFFFu;
            }
        }
        B = m;
    }

    unsigned bd[8];
    int      bi[8];
    #pragma unroll
    for (int j = 0; j < 8; j++) { bd[j] = 0xFFFFFFFFu; bi[j] = -1; }

    // scan only qualifying tiles (warp-uniform branch)
    for (int t = 0; t < NTILE; t++) {
        unsigned tmv = __shfl_sync(0xffffffffu, (t < 32) ? t0 : t1, t & 31);
        if (tmv > B) continue;
        const float* tp = row + (t << 7);
        #pragma unroll
        for (int u = 0; u < 4; u++) {
            int r = lane + (u << 5);
            unsigned v = __float_as_uint(tp[r]);
            if (v < bd[7]) {
                bd[7] = v; bi[7] = (t << 7) + r;
                #pragma unroll
                for (int j = 7; j > 0; --j) {
                    if (bd[j] < bd[j - 1]) {
                        unsigned tv = bd[j]; bd[j] = bd[j - 1]; bd[j - 1] = tv;
                        int      ti = bi[j]; bi[j] = bi[j - 1]; bi[j - 1] = ti;
                    }
                }
            }
        }
    }

    // single warp merge: 16 rounds of head extraction over 32 sorted queues
    int ptr = 0;
    unsigned head = bd[0];
    for (int r = 0; r < TOPK; r++) {
        unsigned m   = __reduce_min_sync(0xffffffffu, head);
        unsigned bal = __ballot_sync(0xffffffffu, head == m);
        int leader   = __ffs(bal) - 1;
        if (lane == leader) {
            g_topIdx[(size_t)q * TOPK + r] = (m < 0x7f800000u) ? bi[ptr] : -1;
            ptr++;
            head = (ptr < 8) ? bd[ptr] : 0xFFFFFFFFu;
        }
    }
}

// ---------------- impute: warp per query, 2 features per lane ---------------
__global__ void impute_kernel(const float* __restrict__ X, float* __restrict__ out)
{
    int q    = blockIdx.x * (blockDim.x >> 5) + (threadIdx.x >> 5);
    int lane = threadIdx.x & 31;
    if (q >= NQ) return;

    int myidx = (lane < TOPK) ? g_topIdx[(size_t)q * TOPK + lane] : -1;

    float v0 = X[(size_t)q * DD + lane];
    float v1 = X[(size_t)q * DD + lane + 32];
    bool  n0 = isnan(v0);
    bool  n1 = isnan(v1);
    float s0 = 0.0f, s1 = 0.0f;
    int   c0 = 0, c1 = 0;

    for (int r = 0; r < TOPK; r++) {
        int i = __shfl_sync(0xffffffffu, myidx, r);
        if (i < 0) break;
        unsigned long long fb = g_fbits[i];
        if (n0 && c0 < KNN && ((fb >> lane) & 1ull)) {
            s0 += g_Fc[(size_t)i * DD + lane]; c0++;
        }
        if (n1 && c1 < KNN && ((fb >> (lane + 32)) & 1ull)) {
            s1 += g_Fc[(size_t)i * DD + lane + 32]; c1++;
        }
        bool done = (!n0 || c0 >= KNN) && (!n1 || c1 >= KNN);
        if (__all_sync(0xffffffffu, done)) break;
    }

    out[(size_t)q * DD + lane]      = n0 ? (c0 ? s0 / (float)c0 : g_colmean[lane])      : v0;
    out[(size_t)q * DD + lane + 32] = n1 ? (c1 ? s1 / (float)c1 : g_colmean[lane + 32]) : v1;
}

// ---------------- launcher ---------------------------------------------------
extern "C" void kernel_launch(void* const* d_in, const int* in_sizes, int n_in,
                              void* d_out, int out_size)
{
    const float* X   = (const float*)d_in[0];
    const float* fit = (const float*)d_in[1];
    float* out = (float*)d_out;
    (void)in_sizes; (void)n_in; (void)out_size;

    cudaFuncSetAttribute(dist_kernel,
                         cudaFuncAttributeMaxDynamicSharedMemorySize, SMEM_BYTES);
    cudaFuncSetAttribute(dist_kernel,
                         cudaFuncAttributePreferredSharedMemoryCarveout,
                         cudaSharedmemCarveoutMaxShared);

    prep_kernel<<<NQ / 8, 256>>>(X, NQ, 1);
    prep_kernel<<<NF / 8, 256>>>(fit, NF, 0);
    colmean_kernel<<<DD, 256>>>(fit);

    dim3 dgrid(NF / BN, NQ / BM);
    dist_kernel<<<dgrid, 256, SMEM_BYTES>>>();

    topk_kernel<<<NQ / 8, 256>>>();

    impute_kernel<<<NQ / 8, 256>>>(X, out);
}